// round 2
// baseline (speedup 1.0000x reference)
#include <cuda_runtime.h>

// Fused capsule layer: per-input-capsule 3x3 SAME conv (votes) + 3-iteration
// dynamic routing, one kernel, votes tile in shared memory.
// R1: 512 threads (occ 12.5%->25%) + packed fma.rn.f32x2 (halves FFMA issue,
//     doubles fp32 rate on sm_103a).
//
// Shapes:
//   x   [B=32, H=32, W=32, IN_CAPS=8, IN_F=16]   fp32
//   W   [8, 3, 3, 16, 128]                        fp32
//   b   [1, 1, 8, 16]                             fp32
//   out [32, 32, 32, 8, 16]                       fp32

#define TH 4
#define TW 8
#define NPX 32
#define IN_CAPS 8
#define EPS_SQ 1e-7f
#define NTHREADS 512

#define SX_ROWS 6          // TH + 2 halo
#define SX_COLS 10         // TW + 2 halo
#define SX_SIZE (SX_ROWS * SX_COLS * 128)   // 7680 floats
#define SV_SIZE (NPX * IN_CAPS * 128)       // 32768 floats
#define SW_SIZE (2 * 16 * 128)              // 4096 floats (double buffer)
#define SMEM_BYTES ((SX_SIZE + SV_SIZE + SW_SIZE) * 4)  // 178176 B

extern __shared__ float smem[];

__device__ __forceinline__ unsigned long long pack2(float x) {
    unsigned long long r;
    asm("mov.b64 %0, {%1, %1};" : "=l"(r) : "f"(x));
    return r;
}
__device__ __forceinline__ void ffma2(unsigned long long& d,
                                      unsigned long long a,
                                      unsigned long long b) {
    asm("fma.rn.f32x2 %0, %1, %2, %0;" : "+l"(d) : "l"(a), "l"(b));
}
__device__ __forceinline__ float2 unpack2(unsigned long long v) {
    float2 f;
    asm("mov.b64 {%0, %1}, %2;" : "=f"(f.x), "=f"(f.y) : "l"(v));
    return f;
}

__global__ __launch_bounds__(NTHREADS, 1)
void caps_fused_kernel(const float* __restrict__ x,
                       const float* __restrict__ Wt,
                       const float* __restrict__ bias,
                       float* __restrict__ out)
{
    float* s_x = smem;                 // [6][10][128]
    float* s_v = smem + SX_SIZE;       // [32 px][8 i][128 cf]
    float* s_w = s_v + SV_SIZE;        // [2][16][128]

    const int t  = threadIdx.x;
    const int b  = blockIdx.z;
    const int h0 = blockIdx.y * TH;
    const int w0 = blockIdx.x * TW;

    // ---------------- load x tile with halo (zero-pad SAME borders) ---------
    {
        const float4* xg = reinterpret_cast<const float4*>(x);
        float4* sx4 = reinterpret_cast<float4*>(s_x);
        for (int e4 = t; e4 < SX_SIZE / 4; e4 += NTHREADS) {
            int row = e4 / (SX_COLS * 32);
            int rem = e4 % (SX_COLS * 32);
            int col = rem / 32;
            int c4  = rem % 32;
            int hh = h0 + row - 1;
            int ww = w0 + col - 1;
            float4 v = make_float4(0.f, 0.f, 0.f, 0.f);
            if (hh >= 0 && hh < 32 && ww >= 0 && ww < 32)
                v = xg[(((b * 32 + hh) * 32 + ww) * 128) / 4 + c4];
            sx4[e4] = v;
        }
    }

    // Thread tiling: cfg = t&31 owns cf 4*cfg..4*cfg+3 (two f32x2 pairs).
    // p = t>>5 (0..15) owns pixel pair px0 = p (rows 0-1), px1 = p+16 (rows 2-3).
    const int cfg = t & 31;
    const int p   = t >> 5;
    const int lx  = p & 7;
    const int ly0 = p >> 3;        // 0 or 1
    const int ly1 = ly0 + 2;       // 2 or 3

    const float4* Wg = reinterpret_cast<const float4*>(Wt);
    float4* sw4w = reinterpret_cast<float4*>(s_w);

    // ---------------- conv phase: 8 GEMMs (M=32px, K=144, N=128) ------------
    for (int i = 0; i < IN_CAPS; i++) {
        unsigned long long acc00 = 0ull, acc01 = 0ull, acc10 = 0ull, acc11 = 0ull;

        for (int k = 0; k < 9; k++) {
            if (k == 0) {
                __syncthreads();   // guard s_w buf0 vs previous i's k=8 compute
                sw4w[t] = Wg[(i * 9 + 0) * 512 + t];
            }
            __syncthreads();       // stage(k) visible; compute(k-1) done
            if (k + 1 < 9) {
                sw4w[((k + 1) & 1) * 512 + t] = Wg[(i * 9 + (k + 1)) * 512 + t];
            }
            const int ky = k / 3, kx = k % 3;
            const float* sx0 = s_x + ((ly0 + ky) * SX_COLS + lx + kx) * 128 + i * 16;
            const float* sx1 = s_x + ((ly1 + ky) * SX_COLS + lx + kx) * 128 + i * 16;
            const ulonglong2* sw2 =
                reinterpret_cast<const ulonglong2*>(s_w + (k & 1) * 2048);
            #pragma unroll
            for (int fin = 0; fin < 16; fin++) {
                ulonglong2 wv = sw2[fin * 32 + cfg];
                unsigned long long x0 = pack2(sx0[fin]);
                unsigned long long x1 = pack2(sx1[fin]);
                ffma2(acc00, x0, wv.x);
                ffma2(acc01, x0, wv.y);
                ffma2(acc10, x1, wv.x);
                ffma2(acc11, x1, wv.y);
            }
        }
        // write votes to smem
        float4* sv4 = reinterpret_cast<float4*>(s_v);
        {
            float2 a0 = unpack2(acc00), a1 = unpack2(acc01);
            sv4[(p * IN_CAPS + i) * 32 + cfg] = make_float4(a0.x, a0.y, a1.x, a1.y);
            float2 b0 = unpack2(acc10), b1 = unpack2(acc11);
            sv4[((p + 16) * IN_CAPS + i) * 32 + cfg] = make_float4(b0.x, b0.y, b1.x, b1.y);
        }
    }
    __syncthreads();

    // ---------------- routing phase: one warp per pixel ---------------------
    // lane = c*4 + fq; lane owns (output capsule c, filters fq*4..fq*4+3)
    const int wid  = t >> 5;       // 0..15
    const int lane = t & 31;
    const float4 bv = reinterpret_cast<const float4*>(bias)[lane];
    const float4* sv4 = reinterpret_cast<const float4*>(s_v);

    for (int q = 0; q < 2; q++) {
        const int px  = wid * 2 + q;
        const int ly  = px >> 3;
        const int lxp = px & 7;

        float4 v[8];
        #pragma unroll
        for (int i = 0; i < 8; i++)
            v[i] = sv4[(px * IN_CAPS + i) * 32 + lane];

        float logit[8];
        #pragma unroll
        for (int i = 0; i < 8; i++) logit[i] = 0.f;

        float4 act = make_float4(0.f, 0.f, 0.f, 0.f);

        #pragma unroll
        for (int r = 0; r < 3; r++) {
            // softmax over output capsules c (lanes differ in bits 2..4)
            float route[8];
            #pragma unroll
            for (int i = 0; i < 8; i++) {
                float m = logit[i];
                m = fmaxf(m, __shfl_xor_sync(0xffffffffu, m, 4));
                m = fmaxf(m, __shfl_xor_sync(0xffffffffu, m, 8));
                m = fmaxf(m, __shfl_xor_sync(0xffffffffu, m, 16));
                float e = __expf(logit[i] - m);
                float s = e;
                s += __shfl_xor_sync(0xffffffffu, s, 4);
                s += __shfl_xor_sync(0xffffffffu, s, 8);
                s += __shfl_xor_sync(0xffffffffu, s, 16);
                route[i] = e / s;
            }
            // preactivate = sum_i route[i]*votes[i] + bias
            float4 pre = bv;
            #pragma unroll
            for (int i = 0; i < 8; i++) {
                pre.x += route[i] * v[i].x;
                pre.y += route[i] * v[i].y;
                pre.z += route[i] * v[i].z;
                pre.w += route[i] * v[i].w;
            }
            // squash over f (16 values across the 4 fq lanes of this c)
            float s2 = pre.x * pre.x + pre.y * pre.y + pre.z * pre.z + pre.w * pre.w;
            s2 += __shfl_xor_sync(0xffffffffu, s2, 1);
            s2 += __shfl_xor_sync(0xffffffffu, s2, 2);
            float scale = s2 / (1.f + s2) * rsqrtf(s2 + EPS_SQ);
            act.x = scale * pre.x;
            act.y = scale * pre.y;
            act.z = scale * pre.z;
            act.w = scale * pre.w;
            if (r < 2) {
                #pragma unroll
                for (int i = 0; i < 8; i++) {
                    float d = v[i].x * act.x + v[i].y * act.y +
                              v[i].z * act.z + v[i].w * act.w;
                    d += __shfl_xor_sync(0xffffffffu, d, 1);
                    d += __shfl_xor_sync(0xffffffffu, d, 2);
                    logit[i] += d;
                }
            }
        }

        const int hh = h0 + ly, ww = w0 + lxp;
        reinterpret_cast<float4*>(out)[(((b * 32 + hh) * 32 + ww) * 128) / 4 + lane] = act;
    }
}

extern "C" void kernel_launch(void* const* d_in, const int* in_sizes, int n_in,
                              void* d_out, int out_size)
{
    const float* x    = (const float*)d_in[0];
    const float* Wt   = (const float*)d_in[1];
    const float* bias = (const float*)d_in[2];
    float* out = (float*)d_out;

    (void)in_sizes; (void)n_in; (void)out_size;

    cudaFuncSetAttribute(caps_fused_kernel,
                         cudaFuncAttributeMaxDynamicSharedMemorySize, SMEM_BYTES);

    dim3 grid(32 / TW, 32 / TH, 32);   // (4, 8, 32)
    caps_fused_kernel<<<grid, NTHREADS, SMEM_BYTES>>>(x, Wt, bias, out);
}

// round 4
// speedup vs baseline: 2.2700x; 2.2700x over previous
#include <cuda_runtime.h>
#include <cstdint>

// Fused capsule layer via legacy tensor path (mma.sync m16n8k8 tf32) +
// fp32 dynamic routing. tcgen05 is unavailable (harness compiles via
// compute_103 virtual arch), so the conv runs on fallback HMMA.
//
//   x   [32,32,32,8,16] f32   W [8,3,3,16,128] f32   b [1,1,8,16] f32
//   out [32,32,32,8,16] f32
//
// Per block: 32-px tile (4 rows x 8 cols). Per input capsule i:
//   votes_i[32 px, 128 cf] = im2col(x)_i[32,144] @ W_i[144,128]
// as 2 m16-tiles x 16 n8-tiles x 18 k8-steps of mma.sync tf32.
// A (im2col) frags built straight into mma fragment layout in smem.
// W frags pre-permuted + tf32-rounded once into a __device__ global.

#define NT 256
#define EPS_SQ 1e-7f
#define XPITCH 132                     // floats per x-tile pixel (pad: banks+align)
#define VP 1028                        // votes pitch in floats per pixel

#define SMO_X 0                        // 60 pix * 132 f * 4 = 31680 B
#define SMO_V 31680                    // 32 * 1028 * 4     = 131584 B
#define SMO_A (31680 + 131584)         // 36 blk * 512      = 18432 B
#define SMO_W (SMO_A + 18432)          // 2 * 24576         = 49152 B
#define SMEM_BYTES (SMO_W + 49152)     // 230848 B

// Pre-permuted tf32 weight fragments:
// [i(8)][kk(18)][nt(16)] blocks of 256B; lane*8: (b0,b1) with
// b0 = W[k=8kk+c4][cf=8nt+g], b1 = same k+4.  (g=lane>>2, c4=lane&3)
__device__ uint32_t g_Wfrag[8 * 18 * 16 * 64];

__device__ __forceinline__ uint32_t tf32_rna(float f) {
    uint32_t u;
    asm("cvt.rna.tf32.f32 %0, %1;" : "=r"(u) : "f"(f));
    return u;
}

__device__ __forceinline__ void mma8(float c[4], const uint4& a, const uint2& b) {
    asm volatile(
        "mma.sync.aligned.m16n8k8.row.col.f32.tf32.tf32.f32 "
        "{%0,%1,%2,%3}, {%4,%5,%6,%7}, {%8,%9}, {%0,%1,%2,%3};"
        : "+f"(c[0]), "+f"(c[1]), "+f"(c[2]), "+f"(c[3])
        : "r"(a.x), "r"(a.y), "r"(a.z), "r"(a.w), "r"(b.x), "r"(b.y));
}

__global__ void prep_weights(const float* __restrict__ W) {
    int gi = blockIdx.x * 256 + threadIdx.x;      // 0..73727
    int lane = gi & 31;
    int nt   = (gi >> 5) & 15;
    int r    = gi >> 9;                           // i*18 + kk
    int kk = r % 18, i = r / 18;
    int g = lane >> 2, c4 = lane & 3;
    int cf = nt * 8 + g;
    int k0 = kk * 8 + c4, k1 = k0 + 4;
    float w0 = W[((i * 9 + (k0 >> 4)) * 16 + (k0 & 15)) * 128 + cf];
    float w1 = W[((i * 9 + (k1 >> 4)) * 16 + (k1 & 15)) * 128 + cf];
    uint2 o;
    o.x = tf32_rna(w0);
    o.y = tf32_rna(w1);
    reinterpret_cast<uint2*>(g_Wfrag)[gi] = o;
}

extern __shared__ char smem_c[];

__global__ __launch_bounds__(NT)
void caps_mma_kernel(const float* __restrict__ x,
                     const float* __restrict__ bias,
                     float* __restrict__ out)
{
    const int t = threadIdx.x, wid = t >> 5, lane = t & 31;
    const int b = blockIdx.z, h0 = blockIdx.y * 4, w0 = blockIdx.x * 8;

    float* s_x = reinterpret_cast<float*>(smem_c + SMO_X);
    float* s_v = reinterpret_cast<float*>(smem_c + SMO_V);
    uint4* s_a = reinterpret_cast<uint4*>(smem_c + SMO_A);

    // ---- x tile with halo: 6 rows x 10 cols x 128c, zero-pad SAME ----
    {
        const float4* xg = reinterpret_cast<const float4*>(x);
        float4* sx4 = reinterpret_cast<float4*>(s_x);
        for (int e = t; e < 60 * 32; e += NT) {
            int pix = e >> 5, c4e = e & 31;
            int hh = h0 + pix / 10 - 1, ww = w0 + pix % 10 - 1;
            float4 v = make_float4(0.f, 0.f, 0.f, 0.f);
            if (hh >= 0 && hh < 32 && ww >= 0 && ww < 32)
                v = xg[((b * 32 + hh) * 32 + ww) * 32 + c4e];
            sx4[pix * 33 + c4e] = v;               // 132 floats = 33 float4
        }
    }

    const int g  = lane >> 2, c4 = lane & 3;
    const int mt = wid & 1,   ng = wid >> 1;       // warp = (m-tile, cf-quarter)

    const uint4* gw4 = reinterpret_cast<const uint4*>(g_Wfrag);
    uint4 wst[6];
    #pragma unroll
    for (int s = 0; s < 6; s++)                    // preload group 0 (i=0)
        wst[s] = gw4[s * 256 + t];

    __syncthreads();                               // x tile ready

    for (int i = 0; i < 8; i++) {
        // ---- build A_i fragments (36 blocks of 512B) ----
        for (int e = wid; e < 36; e += 8) {
            int kk = e >> 1, amt = e & 1;
            int kyx = kk >> 1;
            int ky = kyx / 3, kx = kyx - ky * 3;
            int fin0 = ((kk & 1) << 3) + c4;       // fin of k0; fin0+4 same kyx
            int px0 = amt * 16 + g;
            int pix0 = ((px0 >> 3) + ky) * 10 + (px0 & 7) + kx;
            const float* sp  = s_x + pix0 * XPITCH + i * 16;
            const float* sp1 = sp + 10 * XPITCH;   // px0+8 -> next tile row
            uint4 o;
            o.x = tf32_rna(sp[fin0]);
            o.y = tf32_rna(sp1[fin0]);
            o.z = tf32_rna(sp[fin0 + 4]);
            o.w = tf32_rna(sp1[fin0 + 4]);
            s_a[e * 32 + lane] = o;
        }

        float acc[4][4];
        #pragma unroll
        for (int n = 0; n < 4; n++)
            #pragma unroll
            for (int j = 0; j < 4; j++) acc[n][j] = 0.f;

        for (int grp = 0; grp < 3; grp++) {
            // publish staged 6 weight slices (24KB) to buffer grp&1
            uint4* wbuf = reinterpret_cast<uint4*>(smem_c + SMO_W + (grp & 1) * 24576);
            #pragma unroll
            for (int s = 0; s < 6; s++) wbuf[s * 256 + t] = wst[s];
            // prefetch next group (across i) into regs
            int nxt = i * 3 + grp + 1;
            if (nxt < 24) {
                #pragma unroll
                for (int s = 0; s < 6; s++)
                    wst[s] = gw4[(nxt * 6 + s) * 256 + t];
            }
            __syncthreads();

            const uint2* wb2 = reinterpret_cast<const uint2*>(wbuf);
            #pragma unroll
            for (int s = 0; s < 6; s++) {
                int kk = grp * 6 + s;
                uint4 a = s_a[(kk * 2 + mt) * 32 + lane];
                #pragma unroll
                for (int n = 0; n < 4; n++) {
                    uint2 bb = wb2[(s * 16 + ng * 4 + n) * 32 + lane];
                    mma8(acc[n], a, bb);
                }
            }
        }

        // ---- epilogue: acc -> votes smem ----
        #pragma unroll
        for (int n = 0; n < 4; n++) {
            int cf0 = (ng * 4 + n) * 8 + 2 * c4;
            int px0 = mt * 16 + g;
            float* vp = s_v + px0 * VP + i * 128 + cf0;
            *reinterpret_cast<float2*>(vp) = make_float2(acc[n][0], acc[n][1]);
            *reinterpret_cast<float2*>(vp + 8 * VP) = make_float2(acc[n][2], acc[n][3]);
        }
        __syncthreads();   // votes/A safe for next i (and final: routing)
    }

    // ---- routing: warp routes px = wid*4 + q; lane = c*4 + fq ----
    const float4 bv = reinterpret_cast<const float4*>(bias)[lane];

    for (int q = 0; q < 4; q++) {
        const int px = wid * 4 + q;

        float4 v[8];
        #pragma unroll
        for (int i = 0; i < 8; i++)
            v[i] = *reinterpret_cast<const float4*>(s_v + px * VP + i * 128 + lane * 4);

        float logit[8];
        #pragma unroll
        for (int i = 0; i < 8; i++) logit[i] = 0.f;
        float4 act = make_float4(0.f, 0.f, 0.f, 0.f);

        #pragma unroll
        for (int r = 0; r < 3; r++) {
            float route[8];
            if (r == 0) {
                #pragma unroll
                for (int i = 0; i < 8; i++) route[i] = 0.125f;  // softmax(0)
            } else {
                #pragma unroll
                for (int i = 0; i < 8; i++) {
                    float m = logit[i];
                    m = fmaxf(m, __shfl_xor_sync(0xffffffffu, m, 4));
                    m = fmaxf(m, __shfl_xor_sync(0xffffffffu, m, 8));
                    m = fmaxf(m, __shfl_xor_sync(0xffffffffu, m, 16));
                    float e = __expf(logit[i] - m);
                    float s = e;
                    s += __shfl_xor_sync(0xffffffffu, s, 4);
                    s += __shfl_xor_sync(0xffffffffu, s, 8);
                    s += __shfl_xor_sync(0xffffffffu, s, 16);
                    route[i] = e / s;
                }
            }
            float4 pre = bv;
            #pragma unroll
            for (int i = 0; i < 8; i++) {
                pre.x += route[i] * v[i].x;
                pre.y += route[i] * v[i].y;
                pre.z += route[i] * v[i].z;
                pre.w += route[i] * v[i].w;
            }
            float s2 = pre.x * pre.x + pre.y * pre.y + pre.z * pre.z + pre.w * pre.w;
            s2 += __shfl_xor_sync(0xffffffffu, s2, 1);
            s2 += __shfl_xor_sync(0xffffffffu, s2, 2);
            float scale = s2 / (1.f + s2) * rsqrtf(s2 + EPS_SQ);
            act.x = scale * pre.x;
            act.y = scale * pre.y;
            act.z = scale * pre.z;
            act.w = scale * pre.w;
            if (r < 2) {
                #pragma unroll
                for (int i = 0; i < 8; i++) {
                    float d = v[i].x * act.x + v[i].y * act.y +
                              v[i].z * act.z + v[i].w * act.w;
                    d += __shfl_xor_sync(0xffffffffu, d, 1);
                    d += __shfl_xor_sync(0xffffffffu, d, 2);
                    logit[i] += d;
                }
            }
        }

        const int hh = h0 + (px >> 3), ww = w0 + (px & 7);
        reinterpret_cast<float4*>(out)[((b * 32 + hh) * 32 + ww) * 32 + lane] = act;
    }
}

extern "C" void kernel_launch(void* const* d_in, const int* in_sizes, int n_in,
                              void* d_out, int out_size)
{
    const float* x    = (const float*)d_in[0];
    const float* Wt   = (const float*)d_in[1];
    const float* bias = (const float*)d_in[2];
    float* out = (float*)d_out;
    (void)in_sizes; (void)n_in; (void)out_size;

    cudaFuncSetAttribute(caps_mma_kernel,
                         cudaFuncAttributeMaxDynamicSharedMemorySize, SMEM_BYTES);

    prep_weights<<<288, 256>>>(Wt);
    dim3 grid(4, 8, 32);   // 8-wide x 4-high px tiles, 32 batches = 1024 blocks
    caps_mma_kernel<<<grid, NT, SMEM_BYTES>>>(x, bias, out);
}

// round 5
// speedup vs baseline: 4.4647x; 1.9668x over previous
#include <cuda_runtime.h>
#include <cstdint>

// Capsule layer, two-kernel split:
//   K1 conv_votes: tf32 mma.sync GEMM  votes[i][128px,128cf] -> __device__ scratch
//   K2 routing:    fp32 dynamic routing, one warp per pixel
//
//   x [32,32,32,8,16] f32   W [8,3,3,16,128] f32   b [1,1,8,16] f32
//   out [32,32,32,8,16] f32
//
// votes scratch: [px 32768][i 8 * 128cf] f32 = 134 MB (static __device__).

#define EPS_SQ 1e-7f
#define XT_PITCH 232        // 232 % 32 == 8 -> conflict-free A-frag LDS

__device__ float    g_votes[32768 * 1024];
__device__ uint32_t g_Wfrag[8 * 18 * 16 * 64];

__device__ __forceinline__ uint32_t tf32_rna(float f) {
    uint32_t u;
    asm("cvt.rna.tf32.f32 %0, %1;" : "=r"(u) : "f"(f));
    return u;
}
__device__ __forceinline__ void mma8(float c[4], const uint4& a, const uint2& b) {
    asm volatile(
        "mma.sync.aligned.m16n8k8.row.col.f32.tf32.tf32.f32 "
        "{%0,%1,%2,%3}, {%4,%5,%6,%7}, {%8,%9}, {%0,%1,%2,%3};"
        : "+f"(c[0]), "+f"(c[1]), "+f"(c[2]), "+f"(c[3])
        : "r"(a.x), "r"(a.y), "r"(a.z), "r"(a.w), "r"(b.x), "r"(b.y));
}

// Pre-permuted tf32 weight fragments: [i][kk(18)][nt(16)][lane] uint2,
// (b0,b1) = W[k=8kk+c4][cf=8nt+g], W[k+4][cf].  (g=lane>>2, c4=lane&3)
__global__ void prep_weights(const float* __restrict__ W) {
    int gi = blockIdx.x * 256 + threadIdx.x;      // 0..73727
    int lane = gi & 31;
    int nt   = (gi >> 5) & 15;
    int r    = gi >> 9;                           // i*18 + kk
    int kk = r % 18, i = r / 18;
    int g = lane >> 2, c4 = lane & 3;
    int cf = nt * 8 + g;
    int k0 = kk * 8 + c4, k1 = k0 + 4;
    float w0 = W[((i * 9 + (k0 >> 4)) * 16 + (k0 & 15)) * 128 + cf];
    float w1 = W[((i * 9 + (k1 >> 4)) * 16 + (k1 & 15)) * 128 + cf];
    uint2 o;
    o.x = tf32_rna(w0);
    o.y = tf32_rna(w1);
    reinterpret_cast<uint2*>(g_Wfrag)[gi] = o;
}

// ---- K1: conv votes GEMM. grid (256 m-blocks, 8 i), 256 threads ----
// Block handles px = mblk*128 .. +127 (4 h-rows x 32 w of batch mblk>>3),
// all 128 cf, one input capsule i. M=128 (4 wm x 2 mt x m16),
// N=128 (2 wn x 8 n8), K=144 (18 k8).
__global__ __launch_bounds__(256, 2)
void conv_votes_kernel(const float* __restrict__ x)
{
    __shared__ float x_t[16 * XT_PITCH];   // [fin 16][6 rows * 34 cols]

    const int t = threadIdx.x, lane = t & 31, wid = t >> 5;
    const int mblk = blockIdx.x, i = blockIdx.y;
    const int b = mblk >> 3, h0 = (mblk & 7) << 2;

    // load x tile transposed, zero-pad SAME borders (rows 0/5, cols 0/33)
    for (int e4 = t; e4 < 816; e4 += 256) {
        int pix = e4 >> 2, q = e4 & 3;
        int r = pix / 34, c = pix - r * 34;
        int hh = h0 + r - 1, ww = c - 1;
        float4 v = make_float4(0.f, 0.f, 0.f, 0.f);
        if (hh >= 0 && hh < 32 && ww >= 0 && ww < 32)
            v = reinterpret_cast<const float4*>(x)
                  [((b * 32 + hh) * 32 + ww) * 32 + i * 4 + q];
        x_t[(q * 4 + 0) * XT_PITCH + pix] = v.x;
        x_t[(q * 4 + 1) * XT_PITCH + pix] = v.y;
        x_t[(q * 4 + 2) * XT_PITCH + pix] = v.z;
        x_t[(q * 4 + 3) * XT_PITCH + pix] = v.w;
    }
    __syncthreads();

    const int g = lane >> 2, c4 = lane & 3;
    const int wm = wid >> 1, wn = wid & 1;

    float acc[2][8][4];
    #pragma unroll
    for (int mt = 0; mt < 2; mt++)
        #pragma unroll
        for (int n = 0; n < 8; n++)
            #pragma unroll
            for (int j = 0; j < 4; j++) acc[mt][n][j] = 0.f;

    const uint2* wf = reinterpret_cast<const uint2*>(g_Wfrag) +
                      (i * 18 * 16 + wn * 8) * 32 + lane;

    #pragma unroll 3
    for (int kk = 0; kk < 18; kk++) {
        const int kyx = kk >> 1;
        const int ky = kyx / 3, kx = kyx - ky * 3;
        const int fin0 = ((kk & 1) << 3) + c4;
        uint4 a[2];
        #pragma unroll
        for (int mt = 0; mt < 2; mt++) {
            const float* xp = x_t + fin0 * XT_PITCH +
                              (wm + ky) * 34 + mt * 16 + g + kx;
            a[mt].x = tf32_rna(xp[0]);
            a[mt].y = tf32_rna(xp[8]);
            a[mt].z = tf32_rna(xp[4 * XT_PITCH]);
            a[mt].w = tf32_rna(xp[4 * XT_PITCH + 8]);
        }
        #pragma unroll
        for (int n = 0; n < 8; n++) {
            uint2 bb = wf[(kk * 16 + n) * 32];
            mma8(acc[0][n], a[0], bb);
            mma8(acc[1][n], a[1], bb);
        }
    }

    // store votes: [px][i*128 + cf]
    float* vp = g_votes + (size_t)(mblk * 128) * 1024 +
                i * 128 + wn * 64 + 2 * c4;
    #pragma unroll
    for (int mt = 0; mt < 2; mt++) {
        const int m0 = wm * 32 + mt * 16 + g;
        #pragma unroll
        for (int n = 0; n < 8; n++) {
            float* p0 = vp + (size_t)m0 * 1024 + n * 8;
            *reinterpret_cast<float2*>(p0) =
                make_float2(acc[mt][n][0], acc[mt][n][1]);
            *reinterpret_cast<float2*>(p0 + 8 * 1024) =
                make_float2(acc[mt][n][2], acc[mt][n][3]);
        }
    }
}

// ---- K2: routing. grid 4096, 256 threads; warp w routes px = blk*8+w ----
__global__ __launch_bounds__(256)
void routing_kernel(const float* __restrict__ bias, float* __restrict__ out)
{
    const int t = threadIdx.x, lane = t & 31, wid = t >> 5;
    const int px = blockIdx.x * 8 + wid;

    const float4 bv = reinterpret_cast<const float4*>(bias)[lane];
    const float4* vg = reinterpret_cast<const float4*>(g_votes) + (size_t)px * 256;

    float4 v[8];
    #pragma unroll
    for (int i = 0; i < 8; i++)
        v[i] = vg[i * 32 + lane];

    float logit[8];
    #pragma unroll
    for (int i = 0; i < 8; i++) logit[i] = 0.f;
    float4 act = make_float4(0.f, 0.f, 0.f, 0.f);

    #pragma unroll
    for (int r = 0; r < 3; r++) {
        float route[8];
        if (r == 0) {
            #pragma unroll
            for (int i = 0; i < 8; i++) route[i] = 0.125f;   // softmax(0)
        } else {
            #pragma unroll
            for (int i = 0; i < 8; i++) {
                float m = logit[i];
                m = fmaxf(m, __shfl_xor_sync(0xffffffffu, m, 4));
                m = fmaxf(m, __shfl_xor_sync(0xffffffffu, m, 8));
                m = fmaxf(m, __shfl_xor_sync(0xffffffffu, m, 16));
                float e = __expf(logit[i] - m);
                float s = e;
                s += __shfl_xor_sync(0xffffffffu, s, 4);
                s += __shfl_xor_sync(0xffffffffu, s, 8);
                s += __shfl_xor_sync(0xffffffffu, s, 16);
                route[i] = e / s;
            }
        }
        float4 pre = bv;
        #pragma unroll
        for (int i = 0; i < 8; i++) {
            pre.x += route[i] * v[i].x;
            pre.y += route[i] * v[i].y;
            pre.z += route[i] * v[i].z;
            pre.w += route[i] * v[i].w;
        }
        float s2 = pre.x * pre.x + pre.y * pre.y + pre.z * pre.z + pre.w * pre.w;
        s2 += __shfl_xor_sync(0xffffffffu, s2, 1);
        s2 += __shfl_xor_sync(0xffffffffu, s2, 2);
        float scale = s2 / (1.f + s2) * rsqrtf(s2 + EPS_SQ);
        act.x = scale * pre.x;
        act.y = scale * pre.y;
        act.z = scale * pre.z;
        act.w = scale * pre.w;
        if (r < 2) {
            #pragma unroll
            for (int i = 0; i < 8; i++) {
                float d = v[i].x * act.x + v[i].y * act.y +
                          v[i].z * act.z + v[i].w * act.w;
                d += __shfl_xor_sync(0xffffffffu, d, 1);
                d += __shfl_xor_sync(0xffffffffu, d, 2);
                logit[i] += d;
            }
        }
    }

    reinterpret_cast<float4*>(out)[(size_t)px * 32 + lane] = act;
}

extern "C" void kernel_launch(void* const* d_in, const int* in_sizes, int n_in,
                              void* d_out, int out_size)
{
    const float* x    = (const float*)d_in[0];
    const float* Wt   = (const float*)d_in[1];
    const float* bias = (const float*)d_in[2];
    float* out = (float*)d_out;
    (void)in_sizes; (void)n_in; (void)out_size;

    prep_weights<<<288, 256>>>(Wt);
    dim3 gridA(256, 8);
    conv_votes_kernel<<<gridA, 256>>>(x);
    routing_kernel<<<4096, 256>>>(bias, out);
}